// round 1
// baseline (speedup 1.0000x reference)
#include <cuda_runtime.h>
#include <cstdint>
#include <cstddef>

// Problem constants (shapes fixed by the dataset)
#define FIN   256
#define HID   128
#define OUTD  64
#define MAXN  50176            // 50000 rounded up to multiple of 128
#define MAXE  800000

// Scratch (device globals: allocation-free rule)
__device__ float g_T[(size_t)MAXN * HID];   // post-GEMM node features (edge-gather source)
__device__ float g_A[(size_t)MAXN * HID];   // aggregation buffer A
__device__ float g_B[(size_t)MAXN * HID];   // aggregation buffer B
__device__ float g_dinv[MAXN];              // deg -> rsqrt(deg)

// ---------------------------------------------------------------------------
// Degree / normalization
// ---------------------------------------------------------------------------
__global__ void init_deg_kernel(float* deg, int n) {
    int i = blockIdx.x * blockDim.x + threadIdx.x;
    if (i < n) deg[i] = 1.0f;                 // self-loop contributes 1
}

__global__ void accum_deg_kernel(const int* __restrict__ ei, float* deg, int E) {
    int e = blockIdx.x * blockDim.x + threadIdx.x;
    if (e < E) atomicAdd(&deg[ei[E + e]], 1.0f);   // dst row
}

__global__ void finish_dinv_kernel(float* deg, int n) {
    int i = blockIdx.x * blockDim.x + threadIdx.x;
    if (i < n) deg[i] = rsqrtf(deg[i]);       // deg >= 1 always
}

// ---------------------------------------------------------------------------
// GEMM + fused self-loop/bias epilogue
//   T[row,col]  = (A @ W)[row,col]
//   G[row,col]  = dinv[row]^2 * T[row,col] + bias[col]
// BM=128, BK=32, TM=8, TN=BN/16, 256 threads
// ---------------------------------------------------------------------------
template<int K, int BN>
__global__ void __launch_bounds__(256)
gemm_agg_kernel(const float* __restrict__ A, const float* __restrict__ W,
                const float* __restrict__ bias, const float* __restrict__ dinv,
                float* __restrict__ T, float* __restrict__ G, int n)
{
    constexpr int TM = 8;
    constexpr int TN = BN / 16;
    __shared__ float As[32][128];
    __shared__ float Ws[32][BN];

    const int tid = threadIdx.x;
    const int tx = tid & 15;        // col group
    const int ty = tid >> 4;        // row group
    const int rowBase = blockIdx.x * 128;

    float acc[TM][TN];
    #pragma unroll
    for (int i = 0; i < TM; i++)
        #pragma unroll
        for (int j = 0; j < TN; j++) acc[i][j] = 0.0f;

    // A loader mapping: thread -> (row = tid>>3 [+32*r], kvec = (tid&7)*4)
    const int aRow = tid >> 3;
    const int aKv  = (tid & 7) * 4;
    // W loader mapping
    constexpr int WV    = BN / 4;        // float4s per k-row (32 or 16)
    constexpr int WSTEP = 256 / WV;      // k-rows per pass (8 or 16)
    const int wK = tid / WV;
    const int wC = (tid % WV) * 4;

    for (int kt = 0; kt < K; kt += 32) {
        #pragma unroll
        for (int r = 0; r < 4; r++) {
            int lr = aRow + r * 32;
            int grow = rowBase + lr;
            float4 v = make_float4(0.f, 0.f, 0.f, 0.f);
            if (grow < n)
                v = *reinterpret_cast<const float4*>(A + (size_t)grow * K + kt + aKv);
            As[aKv + 0][lr] = v.x;
            As[aKv + 1][lr] = v.y;
            As[aKv + 2][lr] = v.z;
            As[aKv + 3][lr] = v.w;
        }
        #pragma unroll
        for (int r = 0; r < 32 / WSTEP; r++) {
            int k = wK + r * WSTEP;
            *reinterpret_cast<float4*>(&Ws[k][wC]) =
                *reinterpret_cast<const float4*>(W + (size_t)(kt + k) * BN + wC);
        }
        __syncthreads();

        #pragma unroll
        for (int k = 0; k < 32; k++) {
            float a[TM], b[TN];
            #pragma unroll
            for (int i = 0; i < TM; i++) a[i] = As[k][ty * TM + i];
            #pragma unroll
            for (int j = 0; j < TN; j++) b[j] = Ws[k][tx * TN + j];
            #pragma unroll
            for (int i = 0; i < TM; i++)
                #pragma unroll
                for (int j = 0; j < TN; j++) acc[i][j] += a[i] * b[j];
        }
        __syncthreads();
    }

    // Epilogue: write T and fused agg-init G
    #pragma unroll
    for (int i = 0; i < TM; i++) {
        int row = rowBase + ty * TM + i;
        if (row >= n) break;
        float d2 = dinv[row] * dinv[row];
        #pragma unroll
        for (int jv = 0; jv < TN / 4; jv++) {
            int col = tx * TN + jv * 4;
            float4 t = make_float4(acc[i][jv*4+0], acc[i][jv*4+1],
                                   acc[i][jv*4+2], acc[i][jv*4+3]);
            float4 bs = *reinterpret_cast<const float4*>(bias + col);
            float4 g  = make_float4(d2*t.x + bs.x, d2*t.y + bs.y,
                                    d2*t.z + bs.z, d2*t.w + bs.w);
            size_t idx = (size_t)row * BN + col;
            *reinterpret_cast<float4*>(T + idx) = t;
            *reinterpret_cast<float4*>(G + idx) = g;
        }
    }
}

// ---------------------------------------------------------------------------
// Edge scatter: one warp per edge, 128 floats = 32 lanes x float4,
// vector RED into the aggregation buffer (L2-resident).
// ---------------------------------------------------------------------------
__global__ void __launch_bounds__(256)
edge_scatter_kernel(const int* __restrict__ ei, const float* __restrict__ dinv,
                    const float* __restrict__ tmp, float* __restrict__ agg, int E)
{
    int warp = (blockIdx.x * blockDim.x + threadIdx.x) >> 5;
    int lane = threadIdx.x & 31;
    if (warp >= E) return;
    int src = ei[warp];           // broadcast load
    int dst = ei[E + warp];
    float nrm = dinv[src] * dinv[dst];

    float4 v = *reinterpret_cast<const float4*>(tmp + (size_t)src * HID + lane * 4);
    float* p = agg + (size_t)dst * HID + lane * 4;
    asm volatile("red.global.add.v4.f32 [%0], {%1, %2, %3, %4};"
                 :: "l"(p), "f"(v.x * nrm), "f"(v.y * nrm),
                    "f"(v.z * nrm), "f"(v.w * nrm)
                 : "memory");
}

// ---------------------------------------------------------------------------
// Final layer: (A @ Wlin + blin), fused global max-pool over rows.
// K=128, BN=64, TM=8, TN=4, 256 threads.
// ---------------------------------------------------------------------------
__device__ __forceinline__ void atomicMaxF(float* addr, float v) {
    if (v >= 0.0f) atomicMax((int*)addr, __float_as_int(v));
    else           atomicMin((unsigned int*)addr, __float_as_uint(v));
}

__global__ void init_out_kernel(float* out) {
    if (threadIdx.x < OUTD) out[threadIdx.x] = __int_as_float(0xFF800000); // -inf
}

__global__ void __launch_bounds__(256)
gemm_max_kernel(const float* __restrict__ A, const float* __restrict__ W,
                const float* __restrict__ bias, float* __restrict__ out, int n)
{
    constexpr int K = 128, BN = 64, TM = 8, TN = 4;
    __shared__ float As[32][128];
    __shared__ float Ws[32][BN];
    __shared__ float red[BN][17];

    const int tid = threadIdx.x;
    const int tx = tid & 15;
    const int ty = tid >> 4;
    const int rowBase = blockIdx.x * 128;

    float acc[TM][TN];
    #pragma unroll
    for (int i = 0; i < TM; i++)
        #pragma unroll
        for (int j = 0; j < TN; j++) acc[i][j] = 0.0f;

    const int aRow = tid >> 3;
    const int aKv  = (tid & 7) * 4;
    constexpr int WV    = BN / 4;    // 16
    constexpr int WSTEP = 256 / WV;  // 16
    const int wK = tid / WV;
    const int wC = (tid % WV) * 4;

    for (int kt = 0; kt < K; kt += 32) {
        #pragma unroll
        for (int r = 0; r < 4; r++) {
            int lr = aRow + r * 32;
            int grow = rowBase + lr;
            float4 v = make_float4(0.f, 0.f, 0.f, 0.f);
            if (grow < n)
                v = *reinterpret_cast<const float4*>(A + (size_t)grow * K + kt + aKv);
            As[aKv + 0][lr] = v.x;
            As[aKv + 1][lr] = v.y;
            As[aKv + 2][lr] = v.z;
            As[aKv + 3][lr] = v.w;
        }
        #pragma unroll
        for (int r = 0; r < 32 / WSTEP; r++) {
            int k = wK + r * WSTEP;
            *reinterpret_cast<float4*>(&Ws[k][wC]) =
                *reinterpret_cast<const float4*>(W + (size_t)(kt + k) * BN + wC);
        }
        __syncthreads();
        #pragma unroll
        for (int k = 0; k < 32; k++) {
            float a[TM], b[TN];
            #pragma unroll
            for (int i = 0; i < TM; i++) a[i] = As[k][ty * TM + i];
            #pragma unroll
            for (int j = 0; j < TN; j++) b[j] = Ws[k][tx * TN + j];
            #pragma unroll
            for (int i = 0; i < TM; i++)
                #pragma unroll
                for (int j = 0; j < TN; j++) acc[i][j] += a[i] * b[j];
        }
        __syncthreads();
    }

    float lmax[TN];
    #pragma unroll
    for (int j = 0; j < TN; j++) lmax[j] = __int_as_float(0xFF800000);
    #pragma unroll
    for (int i = 0; i < TM; i++) {
        int row = rowBase + ty * TM + i;
        if (row >= n) break;
        #pragma unroll
        for (int j = 0; j < TN; j++) {
            float v = acc[i][j] + bias[tx * TN + j];
            lmax[j] = fmaxf(lmax[j], v);
        }
    }
    #pragma unroll
    for (int j = 0; j < TN; j++) red[tx * TN + j][ty] = lmax[j];
    __syncthreads();
    if (tid < BN) {
        float m = __int_as_float(0xFF800000);
        #pragma unroll
        for (int t = 0; t < 16; t++) m = fmaxf(m, red[tid][t]);
        atomicMaxF(&out[tid], m);
    }
}

// ---------------------------------------------------------------------------
// Launch
// ---------------------------------------------------------------------------
extern "C" void kernel_launch(void* const* d_in, const int* in_sizes, int n_in,
                              void* d_out, int out_size)
{
    const float* x    = (const float*)d_in[0];
    const int*   ei   = (const int*)  d_in[1];
    // d_in[2] = batch (all zeros, unused)
    const float* W0   = (const float*)d_in[3];
    const float* b0   = (const float*)d_in[4];
    const float* W1   = (const float*)d_in[5];
    const float* b1   = (const float*)d_in[6];
    const float* W2   = (const float*)d_in[7];
    const float* b2   = (const float*)d_in[8];
    const float* Wlin = (const float*)d_in[9];
    const float* blin = (const float*)d_in[10];
    float* out = (float*)d_out;

    const int n = in_sizes[0] / FIN;
    const int E = in_sizes[1] / 2;

    float *pT, *pA, *pB, *pD;
    cudaGetSymbolAddress((void**)&pT, g_T);
    cudaGetSymbolAddress((void**)&pA, g_A);
    cudaGetSymbolAddress((void**)&pB, g_B);
    cudaGetSymbolAddress((void**)&pD, g_dinv);

    const int nodeBlocks = (n + 255) / 256;
    const int edgeBlocks = (E + 255) / 256;
    const int gemmBlocks = (n + 127) / 128;
    const int scatBlocks = (E + 7) / 8;        // 8 warps/block, 1 edge/warp

    // normalization
    init_deg_kernel<<<nodeBlocks, 256>>>(pD, n);
    accum_deg_kernel<<<edgeBlocks, 256>>>(ei, pD, E);
    finish_dinv_kernel<<<nodeBlocks, 256>>>(pD, n);

    // layer 0: x @ W0 -> T ; agg-init A ; scatter T->A
    gemm_agg_kernel<FIN, HID><<<gemmBlocks, 256>>>(x, W0, b0, pD, pT, pA, n);
    edge_scatter_kernel<<<scatBlocks, 256>>>(ei, pD, pT, pA, E);

    // layer 1: A @ W1 -> T ; agg-init B ; scatter T->B
    gemm_agg_kernel<HID, HID><<<gemmBlocks, 256>>>(pA, W1, b1, pD, pT, pB, n);
    edge_scatter_kernel<<<scatBlocks, 256>>>(ei, pD, pT, pB, E);

    // layer 2: B @ W2 -> T ; agg-init A ; scatter T->A
    gemm_agg_kernel<HID, HID><<<gemmBlocks, 256>>>(pB, W2, b2, pD, pT, pA, n);
    edge_scatter_kernel<<<scatBlocks, 256>>>(ei, pD, pT, pA, E);

    // final: A @ Wlin + blin, global max-pool
    init_out_kernel<<<1, 64>>>(out);
    gemm_max_kernel<<<gemmBlocks, 256>>>(pA, Wlin, blin, out, n);
}

// round 2
// speedup vs baseline: 1.0108x; 1.0108x over previous
#include <cuda_runtime.h>
#include <cstdint>
#include <cstddef>

#define FIN   256
#define HID   128
#define OUTD  64
#define MAXN  50176
#define MAXE  800000

__device__ float g_T[(size_t)MAXN * HID];
__device__ float g_A[(size_t)MAXN * HID];
__device__ float g_B[(size_t)MAXN * HID];
__device__ float g_dinv[MAXN];

// ---------------------------------------------------------------------------
// cp.async helpers
// ---------------------------------------------------------------------------
__device__ __forceinline__ void cp_async16(void* smem_dst, const void* gmem_src) {
    uint32_t s = (uint32_t)__cvta_generic_to_shared(smem_dst);
    asm volatile("cp.async.cg.shared.global [%0], [%1], 16;\n" :: "r"(s), "l"(gmem_src));
}
__device__ __forceinline__ void cp_commit() {
    asm volatile("cp.async.commit_group;\n");
}
template<int N>
__device__ __forceinline__ void cp_wait() {
    asm volatile("cp.async.wait_group %0;\n" :: "n"(N));
}

// ---------------------------------------------------------------------------
// Degree / normalization
// ---------------------------------------------------------------------------
__global__ void init_deg_kernel(float* deg, int n) {
    int i = blockIdx.x * blockDim.x + threadIdx.x;
    if (i < n) deg[i] = 1.0f;
}
__global__ void accum_deg_kernel(const int* __restrict__ ei, float* deg, int E) {
    int e = blockIdx.x * blockDim.x + threadIdx.x;
    if (e < E) atomicAdd(&deg[ei[E + e]], 1.0f);
}
__global__ void finish_dinv_kernel(float* deg, int n) {
    int i = blockIdx.x * blockDim.x + threadIdx.x;
    if (i < n) deg[i] = rsqrtf(deg[i]);
}

// ---------------------------------------------------------------------------
// Pipelined GEMM core (BM=128, BK=16, double-buffered cp.async)
//   As stored [row][k] padded to 20 floats/row (conflict-free, 16B-aligned)
//   Ws stored [k][col] (natural)
// ---------------------------------------------------------------------------
#define APAD 20

template<int K, int BN, int TM, int TN>
struct GemmCore {
    // A loader: 128 rows x 16 floats; 512 chunks of 16B; 2 chunks/thread.
    static __device__ __forceinline__
    void loadA(float (*As)[APAD], const float* __restrict__ A,
               int rowBase, int kt, int n, int tid) {
        int row  = tid >> 1;
        int cb   = (tid & 1) * 8;      // float offset: 0 or 8
        int grow = rowBase + row;
        if (grow >= n) grow = n - 1;   // clamp: garbage feeds discarded acc rows
        const float* src = A + (size_t)grow * K + kt + cb;
        cp_async16(&As[row][cb],     src);
        cp_async16(&As[row][cb + 4], src + 4);
    }
    // W loader: 16 x BN floats; (16*BN/4) chunks of 16B.
    static __device__ __forceinline__
    void loadW(float (*Ws)[BN], const float* __restrict__ W, int kt, int tid) {
        constexpr int CPK = BN / 4;          // chunks per k-row
        constexpr int NCH = 16 * CPK;        // total chunks
        #pragma unroll
        for (int r = 0; r < NCH / 256; r++) {
            int ch  = tid + r * 256;
            int k   = ch / CPK;
            int col = (ch % CPK) * 4;
            cp_async16(&Ws[k][col], W + (size_t)(kt + k) * BN + col);
        }
    }
    static __device__ __forceinline__
    void compute(const float (*As)[APAD], const float (*Ws)[BN],
                 float acc[TM][TN], int tx, int ty) {
        #pragma unroll
        for (int kk = 0; kk < 16; kk += 4) {
            float4 a4[TM];
            float  a_[TM][4];
            #pragma unroll
            for (int i = 0; i < TM; i++) {
                a4[i] = *reinterpret_cast<const float4*>(&As[ty * TM + i][kk]);
                a_[i][0] = a4[i].x; a_[i][1] = a4[i].y;
                a_[i][2] = a4[i].z; a_[i][3] = a4[i].w;
            }
            #pragma unroll
            for (int c = 0; c < 4; c++) {
                float bb[TN];
                #pragma unroll
                for (int jv = 0; jv < TN / 4; jv++) {
                    float4 b4 = *reinterpret_cast<const float4*>(
                        &Ws[kk + c][tx * TN + jv * 4]);
                    bb[jv*4+0] = b4.x; bb[jv*4+1] = b4.y;
                    bb[jv*4+2] = b4.z; bb[jv*4+3] = b4.w;
                }
                #pragma unroll
                for (int i = 0; i < TM; i++)
                    #pragma unroll
                    for (int j = 0; j < TN; j++)
                        acc[i][j] += a_[i][c] * bb[j];
            }
        }
    }
};

// ---------------------------------------------------------------------------
// GEMM + fused self-loop/bias epilogue
// ---------------------------------------------------------------------------
template<int K, int BN>
__global__ void __launch_bounds__(256)
gemm_agg_kernel(const float* __restrict__ A, const float* __restrict__ W,
                const float* __restrict__ bias, const float* __restrict__ dinv,
                float* __restrict__ T, float* __restrict__ G, int n)
{
    constexpr int TM = 8;
    constexpr int TN = BN / 16;
    constexpr int NT = K / 16;          // number of k-tiles
    using Core = GemmCore<K, BN, TM, TN>;

    __shared__ float As[2][128][APAD];
    __shared__ float Ws[2][16][BN];

    const int tid = threadIdx.x;
    const int tx = tid & 15;
    const int ty = tid >> 4;
    const int rowBase = blockIdx.x * 128;

    float acc[TM][TN];
    #pragma unroll
    for (int i = 0; i < TM; i++)
        #pragma unroll
        for (int j = 0; j < TN; j++) acc[i][j] = 0.0f;

    // prologue
    Core::loadA(As[0], A, rowBase, 0, n, tid);
    Core::loadW(Ws[0], W, 0, tid);
    cp_commit();

    #pragma unroll 1
    for (int t = 0; t < NT; t++) {
        int cur = t & 1, nxt = cur ^ 1;
        if (t + 1 < NT) {
            Core::loadA(As[nxt], A, rowBase, (t + 1) * 16, n, tid);
            Core::loadW(Ws[nxt], W, (t + 1) * 16, tid);
        }
        cp_commit();
        cp_wait<1>();
        __syncthreads();
        Core::compute(As[cur], Ws[cur], acc, tx, ty);
        __syncthreads();
    }

    // epilogue: write T and fused agg-init G = dinv^2 * T + bias
    #pragma unroll
    for (int i = 0; i < TM; i++) {
        int row = rowBase + ty * TM + i;
        if (row >= n) break;
        float d2 = dinv[row] * dinv[row];
        #pragma unroll
        for (int jv = 0; jv < TN / 4; jv++) {
            int col = tx * TN + jv * 4;
            float4 tv = make_float4(acc[i][jv*4+0], acc[i][jv*4+1],
                                    acc[i][jv*4+2], acc[i][jv*4+3]);
            float4 bs = *reinterpret_cast<const float4*>(bias + col);
            float4 g  = make_float4(d2*tv.x + bs.x, d2*tv.y + bs.y,
                                    d2*tv.z + bs.z, d2*tv.w + bs.w);
            size_t idx = (size_t)row * BN + col;
            *reinterpret_cast<float4*>(T + idx) = tv;
            *reinterpret_cast<float4*>(G + idx) = g;
        }
    }
}

// ---------------------------------------------------------------------------
// Edge scatter: one warp per edge, vector RED
// ---------------------------------------------------------------------------
__global__ void __launch_bounds__(256)
edge_scatter_kernel(const int* __restrict__ ei, const float* __restrict__ dinv,
                    const float* __restrict__ tmp, float* __restrict__ agg, int E)
{
    int warp = (blockIdx.x * blockDim.x + threadIdx.x) >> 5;
    int lane = threadIdx.x & 31;
    if (warp >= E) return;
    int src = ei[warp];
    int dst = ei[E + warp];
    float nrm = dinv[src] * dinv[dst];

    float4 v = *reinterpret_cast<const float4*>(tmp + (size_t)src * HID + lane * 4);
    float* p = agg + (size_t)dst * HID + lane * 4;
    asm volatile("red.global.add.v4.f32 [%0], {%1, %2, %3, %4};"
                 :: "l"(p), "f"(v.x * nrm), "f"(v.y * nrm),
                    "f"(v.z * nrm), "f"(v.w * nrm)
                 : "memory");
}

// ---------------------------------------------------------------------------
// Final layer GEMM + fused global max-pool
// ---------------------------------------------------------------------------
__device__ __forceinline__ void atomicMaxF(float* addr, float v) {
    if (v >= 0.0f) atomicMax((int*)addr, __float_as_int(v));
    else           atomicMin((unsigned int*)addr, __float_as_uint(v));
}

__global__ void init_out_kernel(float* out) {
    if (threadIdx.x < OUTD) out[threadIdx.x] = __int_as_float(0xFF800000);
}

__global__ void __launch_bounds__(256)
gemm_max_kernel(const float* __restrict__ A, const float* __restrict__ W,
                const float* __restrict__ bias, float* __restrict__ out, int n)
{
    constexpr int K = 128, BN = 64, TM = 8, TN = 4;
    constexpr int NT = K / 16;
    using Core = GemmCore<K, BN, TM, TN>;

    __shared__ float As[2][128][APAD];
    __shared__ float Ws[2][16][BN];
    __shared__ float red[BN][17];

    const int tid = threadIdx.x;
    const int tx = tid & 15;
    const int ty = tid >> 4;
    const int rowBase = blockIdx.x * 128;

    float acc[TM][TN];
    #pragma unroll
    for (int i = 0; i < TM; i++)
        #pragma unroll
        for (int j = 0; j < TN; j++) acc[i][j] = 0.0f;

    Core::loadA(As[0], A, rowBase, 0, n, tid);
    Core::loadW(Ws[0], W, 0, tid);
    cp_commit();

    #pragma unroll 1
    for (int t = 0; t < NT; t++) {
        int cur = t & 1, nxt = cur ^ 1;
        if (t + 1 < NT) {
            Core::loadA(As[nxt], A, rowBase, (t + 1) * 16, n, tid);
            Core::loadW(Ws[nxt], W, (t + 1) * 16, tid);
        }
        cp_commit();
        cp_wait<1>();
        __syncthreads();
        Core::compute(As[cur], Ws[cur], acc, tx, ty);
        __syncthreads();
    }

    float lmax[TN];
    #pragma unroll
    for (int j = 0; j < TN; j++) lmax[j] = __int_as_float(0xFF800000);
    #pragma unroll
    for (int i = 0; i < TM; i++) {
        int row = rowBase + ty * TM + i;
        if (row >= n) break;
        #pragma unroll
        for (int j = 0; j < TN; j++)
            lmax[j] = fmaxf(lmax[j], acc[i][j] + bias[tx * TN + j]);
    }
    #pragma unroll
    for (int j = 0; j < TN; j++) red[tx * TN + j][ty] = lmax[j];
    __syncthreads();
    if (tid < BN) {
        float m = __int_as_float(0xFF800000);
        #pragma unroll
        for (int t = 0; t < 16; t++) m = fmaxf(m, red[tid][t]);
        atomicMaxF(&out[tid], m);
    }
}

// ---------------------------------------------------------------------------
// Launch
// ---------------------------------------------------------------------------
extern "C" void kernel_launch(void* const* d_in, const int* in_sizes, int n_in,
                              void* d_out, int out_size)
{
    const float* x    = (const float*)d_in[0];
    const int*   ei   = (const int*)  d_in[1];
    const float* W0   = (const float*)d_in[3];
    const float* b0   = (const float*)d_in[4];
    const float* W1   = (const float*)d_in[5];
    const float* b1   = (const float*)d_in[6];
    const float* W2   = (const float*)d_in[7];
    const float* b2   = (const float*)d_in[8];
    const float* Wlin = (const float*)d_in[9];
    const float* blin = (const float*)d_in[10];
    float* out = (float*)d_out;

    const int n = in_sizes[0] / FIN;
    const int E = in_sizes[1] / 2;

    float *pT, *pA, *pB, *pD;
    cudaGetSymbolAddress((void**)&pT, g_T);
    cudaGetSymbolAddress((void**)&pA, g_A);
    cudaGetSymbolAddress((void**)&pB, g_B);
    cudaGetSymbolAddress((void**)&pD, g_dinv);

    const int nodeBlocks = (n + 255) / 256;
    const int edgeBlocks = (E + 255) / 256;
    const int gemmBlocks = (n + 127) / 128;
    const int scatBlocks = (E + 7) / 8;

    init_deg_kernel<<<nodeBlocks, 256>>>(pD, n);
    accum_deg_kernel<<<edgeBlocks, 256>>>(ei, pD, E);
    finish_dinv_kernel<<<nodeBlocks, 256>>>(pD, n);

    gemm_agg_kernel<FIN, HID><<<gemmBlocks, 256>>>(x, W0, b0, pD, pT, pA, n);
    edge_scatter_kernel<<<scatBlocks, 256>>>(ei, pD, pT, pA, E);

    gemm_agg_kernel<HID, HID><<<gemmBlocks, 256>>>(pA, W1, b1, pD, pT, pB, n);
    edge_scatter_kernel<<<scatBlocks, 256>>>(ei, pD, pT, pB, E);

    gemm_agg_kernel<HID, HID><<<gemmBlocks, 256>>>(pB, W2, b2, pD, pT, pA, n);
    edge_scatter_kernel<<<scatBlocks, 256>>>(ei, pD, pT, pA, E);

    init_out_kernel<<<1, 64>>>(out);
    gemm_max_kernel<<<gemmBlocks, 256>>>(pA, Wlin, blin, out, n);
}

// round 3
// speedup vs baseline: 1.0557x; 1.0444x over previous
#include <cuda_runtime.h>
#include <cstdint>
#include <cstddef>

#define FIN   256
#define HID   128
#define OUTD  64
#define MAXN  50176
#define MAXE  800000

typedef unsigned long long ull;

__device__ float g_T[(size_t)MAXN * HID];
__device__ float g_A[(size_t)MAXN * HID];
__device__ float g_B[(size_t)MAXN * HID];
__device__ float g_dinv[MAXN];

// ---------------------------------------------------------------------------
// PTX helpers
// ---------------------------------------------------------------------------
__device__ __forceinline__ void cp_async16(void* smem_dst, const void* gmem_src) {
    uint32_t s = (uint32_t)__cvta_generic_to_shared(smem_dst);
    asm volatile("cp.async.cg.shared.global [%0], [%1], 16;\n" :: "r"(s), "l"(gmem_src));
}
__device__ __forceinline__ void cp_commit() {
    asm volatile("cp.async.commit_group;\n");
}
template<int N>
__device__ __forceinline__ void cp_wait() {
    asm volatile("cp.async.wait_group %0;\n" :: "n"(N));
}
// packed 2-wide FMA: d.lo += a.lo*b.lo ; d.hi += a.hi*b.hi (FFMA2)
__device__ __forceinline__ void fma_x2(ull& d, ull a, ull b) {
    asm("fma.rn.f32x2 %0, %1, %2, %0;" : "+l"(d) : "l"(a), "l"(b));
}
__device__ __forceinline__ ull dup_f32(float a) {
    ull r;
    asm("mov.b64 %0, {%1, %1};" : "=l"(r) : "f"(a));
    return r;
}

// ---------------------------------------------------------------------------
// Degree / normalization
// ---------------------------------------------------------------------------
__global__ void init_deg_kernel(float* deg, int n) {
    int i = blockIdx.x * blockDim.x + threadIdx.x;
    if (i < n) deg[i] = 1.0f;
}
__global__ void accum_deg_kernel(const int* __restrict__ ei, float* deg, int E) {
    int e = blockIdx.x * blockDim.x + threadIdx.x;
    if (e < E) atomicAdd(&deg[ei[E + e]], 1.0f);
}
__global__ void finish_dinv_kernel(float* deg, int n) {
    int i = blockIdx.x * blockDim.x + threadIdx.x;
    if (i < n) deg[i] = rsqrtf(deg[i]);
}

// ---------------------------------------------------------------------------
// Pipelined GEMM core (BM=128, BK=16, double-buffered cp.async, FFMA2 inner)
// ---------------------------------------------------------------------------
#define APAD 20

template<int K, int BN, int TM, int TN>
struct GemmCore {
    static constexpr int NP = TN / 2;   // packed accumulator pairs per row

    static __device__ __forceinline__
    void loadA(float (*As)[APAD], const float* __restrict__ A,
               int rowBase, int kt, int n, int tid) {
        int row  = tid >> 1;
        int cb   = (tid & 1) * 8;
        int grow = rowBase + row;
        if (grow >= n) grow = n - 1;
        const float* src = A + (size_t)grow * K + kt + cb;
        cp_async16(&As[row][cb],     src);
        cp_async16(&As[row][cb + 4], src + 4);
    }
    static __device__ __forceinline__
    void loadW(float (*Ws)[BN], const float* __restrict__ W, int kt, int tid) {
        constexpr int CPK = BN / 4;
        constexpr int NCH = 16 * CPK;
        #pragma unroll
        for (int r = 0; r < NCH / 256; r++) {
            int ch  = tid + r * 256;
            int k   = ch / CPK;
            int col = (ch % CPK) * 4;
            cp_async16(&Ws[k][col], W + (size_t)(kt + k) * BN + col);
        }
    }
    static __device__ __forceinline__
    void compute(const float (*As)[APAD], const float (*Ws)[BN],
                 ull acc[TM][NP], int tx, int ty) {
        #pragma unroll
        for (int kk = 0; kk < 16; kk += 4) {
            float4 a4[TM];
            #pragma unroll
            for (int i = 0; i < TM; i++)
                a4[i] = *reinterpret_cast<const float4*>(&As[ty * TM + i][kk]);
            #pragma unroll
            for (int c = 0; c < 4; c++) {
                ull bp[NP];
                #pragma unroll
                for (int jv = 0; jv < NP / 2; jv++) {
                    ulonglong2 u = *reinterpret_cast<const ulonglong2*>(
                        &Ws[kk + c][tx * TN + jv * 4]);
                    bp[jv * 2 + 0] = u.x;
                    bp[jv * 2 + 1] = u.y;
                }
                #pragma unroll
                for (int i = 0; i < TM; i++) {
                    float av = (c == 0) ? a4[i].x : (c == 1) ? a4[i].y
                             : (c == 2) ? a4[i].z : a4[i].w;
                    ull ad = dup_f32(av);
                    #pragma unroll
                    for (int p = 0; p < NP; p++)
                        fma_x2(acc[i][p], ad, bp[p]);
                }
            }
        }
    }
};

// ---------------------------------------------------------------------------
// GEMM + fused self-loop/bias epilogue
// ---------------------------------------------------------------------------
template<int K, int BN>
__global__ void __launch_bounds__(256)
gemm_agg_kernel(const float* __restrict__ A, const float* __restrict__ W,
                const float* __restrict__ bias, const float* __restrict__ dinv,
                float* __restrict__ T, float* __restrict__ G, int n)
{
    constexpr int TM = 8;
    constexpr int TN = BN / 16;
    constexpr int NP = TN / 2;
    constexpr int NT = K / 16;
    using Core = GemmCore<K, BN, TM, TN>;

    __shared__ float As[2][128][APAD];
    __shared__ float Ws[2][16][BN];

    const int tid = threadIdx.x;
    const int tx = tid & 15;
    const int ty = tid >> 4;
    const int rowBase = blockIdx.x * 128;

    ull acc[TM][NP];
    #pragma unroll
    for (int i = 0; i < TM; i++)
        #pragma unroll
        for (int p = 0; p < NP; p++) acc[i][p] = 0ULL;

    Core::loadA(As[0], A, rowBase, 0, n, tid);
    Core::loadW(Ws[0], W, 0, tid);
    cp_commit();

    #pragma unroll 1
    for (int t = 0; t < NT; t++) {
        int cur = t & 1, nxt = cur ^ 1;
        if (t + 1 < NT) {
            Core::loadA(As[nxt], A, rowBase, (t + 1) * 16, n, tid);
            Core::loadW(Ws[nxt], W, (t + 1) * 16, tid);
        }
        cp_commit();
        cp_wait<1>();
        __syncthreads();
        Core::compute(As[cur], Ws[cur], acc, tx, ty);
        __syncthreads();
    }

    #pragma unroll
    for (int i = 0; i < TM; i++) {
        int row = rowBase + ty * TM + i;
        if (row >= n) break;
        float d2 = dinv[row] * dinv[row];
        #pragma unroll
        for (int jv = 0; jv < NP / 2; jv++) {
            int col = tx * TN + jv * 4;
            float2 p0 = *reinterpret_cast<float2*>(&acc[i][jv * 2 + 0]);
            float2 p1 = *reinterpret_cast<float2*>(&acc[i][jv * 2 + 1]);
            float4 tv = make_float4(p0.x, p0.y, p1.x, p1.y);
            float4 bs = *reinterpret_cast<const float4*>(bias + col);
            float4 g  = make_float4(d2*tv.x + bs.x, d2*tv.y + bs.y,
                                    d2*tv.z + bs.z, d2*tv.w + bs.w);
            size_t idx = (size_t)row * BN + col;
            *reinterpret_cast<float4*>(T + idx) = tv;
            *reinterpret_cast<float4*>(G + idx) = g;
        }
    }
}

// ---------------------------------------------------------------------------
// Edge scatter: one warp per edge, vector RED
// ---------------------------------------------------------------------------
__global__ void __launch_bounds__(256)
edge_scatter_kernel(const int* __restrict__ ei, const float* __restrict__ dinv,
                    const float* __restrict__ tmp, float* __restrict__ agg, int E)
{
    int warp = (blockIdx.x * blockDim.x + threadIdx.x) >> 5;
    int lane = threadIdx.x & 31;
    if (warp >= E) return;
    int src = ei[warp];
    int dst = ei[E + warp];
    float nrm = dinv[src] * dinv[dst];

    float4 v = *reinterpret_cast<const float4*>(tmp + (size_t)src * HID + lane * 4);
    float* p = agg + (size_t)dst * HID + lane * 4;
    asm volatile("red.global.add.v4.f32 [%0], {%1, %2, %3, %4};"
                 :: "l"(p), "f"(v.x * nrm), "f"(v.y * nrm),
                    "f"(v.z * nrm), "f"(v.w * nrm)
                 : "memory");
}

// ---------------------------------------------------------------------------
// Final layer GEMM + fused global max-pool
// ---------------------------------------------------------------------------
__device__ __forceinline__ void atomicMaxF(float* addr, float v) {
    if (v >= 0.0f) atomicMax((int*)addr, __float_as_int(v));
    else           atomicMin((unsigned int*)addr, __float_as_uint(v));
}

__global__ void init_out_kernel(float* out) {
    if (threadIdx.x < OUTD) out[threadIdx.x] = __int_as_float(0xFF800000);
}

__global__ void __launch_bounds__(256)
gemm_max_kernel(const float* __restrict__ A, const float* __restrict__ W,
                const float* __restrict__ bias, float* __restrict__ out, int n)
{
    constexpr int K = 128, BN = 64, TM = 8, TN = 4;
    constexpr int NP = TN / 2;
    constexpr int NT = K / 16;
    using Core = GemmCore<K, BN, TM, TN>;

    __shared__ float As[2][128][APAD];
    __shared__ float Ws[2][16][BN];
    __shared__ float red[BN][17];

    const int tid = threadIdx.x;
    const int tx = tid & 15;
    const int ty = tid >> 4;
    const int rowBase = blockIdx.x * 128;

    ull acc[TM][NP];
    #pragma unroll
    for (int i = 0; i < TM; i++)
        #pragma unroll
        for (int p = 0; p < NP; p++) acc[i][p] = 0ULL;

    Core::loadA(As[0], A, rowBase, 0, n, tid);
    Core::loadW(Ws[0], W, 0, tid);
    cp_commit();

    #pragma unroll 1
    for (int t = 0; t < NT; t++) {
        int cur = t & 1, nxt = cur ^ 1;
        if (t + 1 < NT) {
            Core::loadA(As[nxt], A, rowBase, (t + 1) * 16, n, tid);
            Core::loadW(Ws[nxt], W, (t + 1) * 16, tid);
        }
        cp_commit();
        cp_wait<1>();
        __syncthreads();
        Core::compute(As[cur], Ws[cur], acc, tx, ty);
        __syncthreads();
    }

    float lmax[TN];
    #pragma unroll
    for (int j = 0; j < TN; j++) lmax[j] = __int_as_float(0xFF800000);
    #pragma unroll
    for (int i = 0; i < TM; i++) {
        int row = rowBase + ty * TM + i;
        if (row >= n) break;
        #pragma unroll
        for (int p = 0; p < NP; p++) {
            float2 v = *reinterpret_cast<float2*>(&acc[i][p]);
            lmax[p*2+0] = fmaxf(lmax[p*2+0], v.x + bias[tx * TN + p*2+0]);
            lmax[p*2+1] = fmaxf(lmax[p*2+1], v.y + bias[tx * TN + p*2+1]);
        }
    }
    #pragma unroll
    for (int j = 0; j < TN; j++) red[tx * TN + j][ty] = lmax[j];
    __syncthreads();
    if (tid < BN) {
        float m = __int_as_float(0xFF800000);
        #pragma unroll
        for (int t = 0; t < 16; t++) m = fmaxf(m, red[tid][t]);
        atomicMaxF(&out[tid], m);
    }
}

// ---------------------------------------------------------------------------
// Launch
// ---------------------------------------------------------------------------
extern "C" void kernel_launch(void* const* d_in, const int* in_sizes, int n_in,
                              void* d_out, int out_size)
{
    const float* x    = (const float*)d_in[0];
    const int*   ei   = (const int*)  d_in[1];
    const float* W0   = (const float*)d_in[3];
    const float* b0   = (const float*)d_in[4];
    const float* W1   = (const float*)d_in[5];
    const float* b1   = (const float*)d_in[6];
    const float* W2   = (const float*)d_in[7];
    const float* b2   = (const float*)d_in[8];
    const float* Wlin = (const float*)d_in[9];
    const float* blin = (const float*)d_in[10];
    float* out = (float*)d_out;

    const int n = in_sizes[0] / FIN;
    const int E = in_sizes[1] / 2;

    float *pT, *pA, *pB, *pD;
    cudaGetSymbolAddress((void**)&pT, g_T);
    cudaGetSymbolAddress((void**)&pA, g_A);
    cudaGetSymbolAddress((void**)&pB, g_B);
    cudaGetSymbolAddress((void**)&pD, g_dinv);

    const int nodeBlocks = (n + 255) / 256;
    const int edgeBlocks = (E + 255) / 256;
    const int gemmBlocks = (n + 127) / 128;
    const int scatBlocks = (E + 7) / 8;

    init_deg_kernel<<<nodeBlocks, 256>>>(pD, n);
    accum_deg_kernel<<<edgeBlocks, 256>>>(ei, pD, E);
    finish_dinv_kernel<<<nodeBlocks, 256>>>(pD, n);

    gemm_agg_kernel<FIN, HID><<<gemmBlocks, 256>>>(x, W0, b0, pD, pT, pA, n);
    edge_scatter_kernel<<<scatBlocks, 256>>>(ei, pD, pT, pA, E);

    gemm_agg_kernel<HID, HID><<<gemmBlocks, 256>>>(pA, W1, b1, pD, pT, pB, n);
    edge_scatter_kernel<<<scatBlocks, 256>>>(ei, pD, pT, pB, E);

    gemm_agg_kernel<HID, HID><<<gemmBlocks, 256>>>(pB, W2, b2, pD, pT, pA, n);
    edge_scatter_kernel<<<scatBlocks, 256>>>(ei, pD, pT, pA, E);

    init_out_kernel<<<1, 64>>>(out);
    gemm_max_kernel<<<gemmBlocks, 256>>>(pA, Wlin, blin, out, n);
}

// round 4
// speedup vs baseline: 1.6634x; 1.5756x over previous
#include <cuda_runtime.h>
#include <cstdint>
#include <cstddef>

#define FIN   256
#define HID   128
#define OUTD  64
#define MAXN  50176
#define MAXE  800000
#define SCAN_B 256

typedef unsigned long long ull;

__device__ float g_T[(size_t)MAXN * HID];
__device__ float g_A[(size_t)MAXN * HID];
__device__ float g_B[(size_t)MAXN * HID];
__device__ float g_dinv[MAXN];
__device__ int   g_cnt[MAXN];
__device__ int   g_offs[MAXN];
__device__ int   g_cursor[MAXN];
__device__ int   g_bsum[SCAN_B];
__device__ int   g_bbase[SCAN_B];
__device__ int   g_ssrc[MAXE];

// ---------------------------------------------------------------------------
// PTX helpers
// ---------------------------------------------------------------------------
__device__ __forceinline__ void cp_async16(void* smem_dst, const void* gmem_src) {
    uint32_t s = (uint32_t)__cvta_generic_to_shared(smem_dst);
    asm volatile("cp.async.cg.shared.global [%0], [%1], 16;\n" :: "r"(s), "l"(gmem_src));
}
__device__ __forceinline__ void cp_commit() {
    asm volatile("cp.async.commit_group;\n");
}
template<int N>
__device__ __forceinline__ void cp_wait() {
    asm volatile("cp.async.wait_group %0;\n" :: "n"(N));
}
__device__ __forceinline__ void fma_x2(ull& d, ull a, ull b) {
    asm("fma.rn.f32x2 %0, %1, %2, %0;" : "+l"(d) : "l"(a), "l"(b));
}
__device__ __forceinline__ ull dup_f32(float a) {
    ull r;
    asm("mov.b64 %0, {%1, %1};" : "=l"(r) : "f"(a));
    return r;
}

// ---------------------------------------------------------------------------
// CSR build: histogram -> block scan -> scatter
// ---------------------------------------------------------------------------
__global__ void zero_cnt_kernel(int* cnt, int n) {
    int i = blockIdx.x * blockDim.x + threadIdx.x;
    if (i < n) cnt[i] = 0;
}
__global__ void hist_kernel(const int* __restrict__ ei, int* cnt, int E) {
    int e = blockIdx.x * blockDim.x + threadIdx.x;
    if (e < E) atomicAdd(&cnt[ei[E + e]], 1);
}
// per-block inclusive scan -> exclusive offsets within block + block totals
__global__ void scan_block_kernel(const int* __restrict__ cnt, int* offs,
                                  int* bsum, int n) {
    __shared__ int sm[SCAN_B];
    int i = blockIdx.x * SCAN_B + threadIdx.x;
    int v = (i < n) ? cnt[i] : 0;
    sm[threadIdx.x] = v;
    __syncthreads();
    #pragma unroll
    for (int o = 1; o < SCAN_B; o <<= 1) {
        int y = (threadIdx.x >= o) ? sm[threadIdx.x - o] : 0;
        __syncthreads();
        sm[threadIdx.x] += y;
        __syncthreads();
    }
    if (i < n) offs[i] = sm[threadIdx.x] - v;       // exclusive within block
    if (threadIdx.x == SCAN_B - 1) bsum[blockIdx.x] = sm[SCAN_B - 1];
}
// single-block scan of block sums -> exclusive block bases
__global__ void scan_top_kernel(const int* __restrict__ bsum, int* bbase, int nb) {
    __shared__ int sm[SCAN_B];
    int v = (threadIdx.x < nb) ? bsum[threadIdx.x] : 0;
    sm[threadIdx.x] = v;
    __syncthreads();
    #pragma unroll
    for (int o = 1; o < SCAN_B; o <<= 1) {
        int y = (threadIdx.x >= o) ? sm[threadIdx.x - o] : 0;
        __syncthreads();
        sm[threadIdx.x] += y;
        __syncthreads();
    }
    if (threadIdx.x < nb) bbase[threadIdx.x] = sm[threadIdx.x] - v;
}
// add bases, init cursor, and compute dinv = rsqrt(indeg + 1)
__global__ void finalize_offs_kernel(int* offs, const int* __restrict__ bbase,
                                     int* cursor, const int* __restrict__ cnt,
                                     float* dinv, int n) {
    int i = blockIdx.x * blockDim.x + threadIdx.x;
    if (i < n) {
        int o = offs[i] + bbase[i / SCAN_B];
        offs[i] = o;
        cursor[i] = o;
        dinv[i] = rsqrtf((float)(cnt[i] + 1));
    }
}
__global__ void scatter_edges_kernel(const int* __restrict__ ei, int* cursor,
                                     int* ssrc, int E) {
    int e = blockIdx.x * blockDim.x + threadIdx.x;
    if (e < E) {
        int s = ei[e];
        int d = ei[E + e];
        int p = atomicAdd(&cursor[d], 1);
        ssrc[p] = s;
    }
}

// ---------------------------------------------------------------------------
// Pipelined GEMM core (BM=128, BK=16, double-buffered cp.async, FFMA2 inner)
// ---------------------------------------------------------------------------
#define APAD 20

template<int K, int BN, int TM, int TN>
struct GemmCore {
    static constexpr int NP = TN / 2;

    static __device__ __forceinline__
    void loadA(float (*As)[APAD], const float* __restrict__ A,
               int rowBase, int kt, int n, int tid) {
        int row  = tid >> 1;
        int cb   = (tid & 1) * 8;
        int grow = rowBase + row;
        if (grow >= n) grow = n - 1;
        const float* src = A + (size_t)grow * K + kt + cb;
        cp_async16(&As[row][cb],     src);
        cp_async16(&As[row][cb + 4], src + 4);
    }
    static __device__ __forceinline__
    void loadW(float (*Ws)[BN], const float* __restrict__ W, int kt, int tid) {
        constexpr int CPK = BN / 4;
        constexpr int NCH = 16 * CPK;
        #pragma unroll
        for (int r = 0; r < NCH / 256; r++) {
            int ch  = tid + r * 256;
            int k   = ch / CPK;
            int col = (ch % CPK) * 4;
            cp_async16(&Ws[k][col], W + (size_t)(kt + k) * BN + col);
        }
    }
    static __device__ __forceinline__
    void compute(const float (*As)[APAD], const float (*Ws)[BN],
                 ull acc[TM][NP], int tx, int ty) {
        #pragma unroll
        for (int kk = 0; kk < 16; kk += 4) {
            float4 a4[TM];
            #pragma unroll
            for (int i = 0; i < TM; i++)
                a4[i] = *reinterpret_cast<const float4*>(&As[ty * TM + i][kk]);
            #pragma unroll
            for (int c = 0; c < 4; c++) {
                ull bp[NP];
                #pragma unroll
                for (int jv = 0; jv < NP / 2; jv++) {
                    ulonglong2 u = *reinterpret_cast<const ulonglong2*>(
                        &Ws[kk + c][tx * TN + jv * 4]);
                    bp[jv * 2 + 0] = u.x;
                    bp[jv * 2 + 1] = u.y;
                }
                #pragma unroll
                for (int i = 0; i < TM; i++) {
                    float av = (c == 0) ? a4[i].x : (c == 1) ? a4[i].y
                             : (c == 2) ? a4[i].z : a4[i].w;
                    ull ad = dup_f32(av);
                    #pragma unroll
                    for (int p = 0; p < NP; p++)
                        fma_x2(acc[i][p], ad, bp[p]);
                }
            }
        }
    }
};

// ---------------------------------------------------------------------------
// Plain GEMM: T = A @ W  (aggregation handles self-loop + bias)
// ---------------------------------------------------------------------------
template<int K, int BN>
__global__ void __launch_bounds__(256, 2)
gemm_kernel(const float* __restrict__ A, const float* __restrict__ W,
            float* __restrict__ T, int n)
{
    constexpr int TM = 8;
    constexpr int TN = BN / 16;
    constexpr int NP = TN / 2;
    constexpr int NT = K / 16;
    using Core = GemmCore<K, BN, TM, TN>;

    __shared__ float As[2][128][APAD];
    __shared__ float Ws[2][16][BN];

    const int tid = threadIdx.x;
    const int tx = tid & 15;
    const int ty = tid >> 4;
    const int rowBase = blockIdx.x * 128;

    ull acc[TM][NP];
    #pragma unroll
    for (int i = 0; i < TM; i++)
        #pragma unroll
        for (int p = 0; p < NP; p++) acc[i][p] = 0ULL;

    Core::loadA(As[0], A, rowBase, 0, n, tid);
    Core::loadW(Ws[0], W, 0, tid);
    cp_commit();

    #pragma unroll 1
    for (int t = 0; t < NT; t++) {
        int cur = t & 1, nxt = cur ^ 1;
        if (t + 1 < NT) {
            Core::loadA(As[nxt], A, rowBase, (t + 1) * 16, n, tid);
            Core::loadW(Ws[nxt], W, (t + 1) * 16, tid);
        }
        cp_commit();
        cp_wait<1>();
        __syncthreads();
        Core::compute(As[cur], Ws[cur], acc, tx, ty);
        __syncthreads();
    }

    #pragma unroll
    for (int i = 0; i < TM; i++) {
        int row = rowBase + ty * TM + i;
        if (row >= n) break;
        #pragma unroll
        for (int jv = 0; jv < NP / 2; jv++) {
            int col = tx * TN + jv * 4;
            float2 p0 = *reinterpret_cast<float2*>(&acc[i][jv * 2 + 0]);
            float2 p1 = *reinterpret_cast<float2*>(&acc[i][jv * 2 + 1]);
            float4 tv = make_float4(p0.x, p0.y, p1.x, p1.y);
            *reinterpret_cast<float4*>(T + (size_t)row * BN + col) = tv;
        }
    }
}

// ---------------------------------------------------------------------------
// Gather aggregation: one warp per node, CSR row walk, no atomics.
//   G[v] = dinv[v]^2 * T[v] + bias + sum_{e:(s->v)} dinv[s]*dinv[v]*T[s]
// ---------------------------------------------------------------------------
__global__ void __launch_bounds__(128)
agg_gather_kernel(const int* __restrict__ ssrc, const int* __restrict__ offs,
                  const int* __restrict__ cnt, const float* __restrict__ dinv,
                  const float* __restrict__ bias, const float* __restrict__ T,
                  float* __restrict__ G, int n)
{
    int node = blockIdx.x * 4 + (threadIdx.x >> 5);
    if (node >= n) return;
    int lane = threadIdx.x & 31;

    float dv = dinv[node];
    float4 t = *reinterpret_cast<const float4*>(T + (size_t)node * HID + lane * 4);
    float4 b = *reinterpret_cast<const float4*>(bias + lane * 4);
    float d2 = dv * dv;
    float4 acc = make_float4(d2 * t.x + b.x, d2 * t.y + b.y,
                             d2 * t.z + b.z, d2 * t.w + b.w);

    int beg = offs[node];
    int end = beg + cnt[node];
    int e = beg;
    // 2-wide unroll for MLP
    for (; e + 1 < end; e += 2) {
        int s0 = ssrc[e], s1 = ssrc[e + 1];
        float n0 = dinv[s0] * dv, n1 = dinv[s1] * dv;
        float4 v0 = *reinterpret_cast<const float4*>(T + (size_t)s0 * HID + lane * 4);
        float4 v1 = *reinterpret_cast<const float4*>(T + (size_t)s1 * HID + lane * 4);
        acc.x += n0 * v0.x + n1 * v1.x;
        acc.y += n0 * v0.y + n1 * v1.y;
        acc.z += n0 * v0.z + n1 * v1.z;
        acc.w += n0 * v0.w + n1 * v1.w;
    }
    if (e < end) {
        int s0 = ssrc[e];
        float n0 = dinv[s0] * dv;
        float4 v0 = *reinterpret_cast<const float4*>(T + (size_t)s0 * HID + lane * 4);
        acc.x += n0 * v0.x; acc.y += n0 * v0.y;
        acc.z += n0 * v0.z; acc.w += n0 * v0.w;
    }
    *reinterpret_cast<float4*>(G + (size_t)node * HID + lane * 4) = acc;
}

// ---------------------------------------------------------------------------
// Final layer GEMM + fused global max-pool
// ---------------------------------------------------------------------------
__device__ __forceinline__ void atomicMaxF(float* addr, float v) {
    if (v >= 0.0f) atomicMax((int*)addr, __float_as_int(v));
    else           atomicMin((unsigned int*)addr, __float_as_uint(v));
}

__global__ void init_out_kernel(float* out) {
    if (threadIdx.x < OUTD) out[threadIdx.x] = __int_as_float(0xFF800000);
}

__global__ void __launch_bounds__(256, 2)
gemm_max_kernel(const float* __restrict__ A, const float* __restrict__ W,
                const float* __restrict__ bias, float* __restrict__ out, int n)
{
    constexpr int K = 128, BN = 64, TM = 8, TN = 4;
    constexpr int NP = TN / 2;
    constexpr int NT = K / 16;
    using Core = GemmCore<K, BN, TM, TN>;

    __shared__ float As[2][128][APAD];
    __shared__ float Ws[2][16][BN];
    __shared__ float red[BN][17];

    const int tid = threadIdx.x;
    const int tx = tid & 15;
    const int ty = tid >> 4;
    const int rowBase = blockIdx.x * 128;

    ull acc[TM][NP];
    #pragma unroll
    for (int i = 0; i < TM; i++)
        #pragma unroll
        for (int p = 0; p < NP; p++) acc[i][p] = 0ULL;

    Core::loadA(As[0], A, rowBase, 0, n, tid);
    Core::loadW(Ws[0], W, 0, tid);
    cp_commit();

    #pragma unroll 1
    for (int t = 0; t < NT; t++) {
        int cur = t & 1, nxt = cur ^ 1;
        if (t + 1 < NT) {
            Core::loadA(As[nxt], A, rowBase, (t + 1) * 16, n, tid);
            Core::loadW(Ws[nxt], W, (t + 1) * 16, tid);
        }
        cp_commit();
        cp_wait<1>();
        __syncthreads();
        Core::compute(As[cur], Ws[cur], acc, tx, ty);
        __syncthreads();
    }

    float lmax[TN];
    #pragma unroll
    for (int j = 0; j < TN; j++) lmax[j] = __int_as_float(0xFF800000);
    #pragma unroll
    for (int i = 0; i < TM; i++) {
        int row = rowBase + ty * TM + i;
        if (row >= n) break;
        #pragma unroll
        for (int p = 0; p < NP; p++) {
            float2 v = *reinterpret_cast<float2*>(&acc[i][p]);
            lmax[p*2+0] = fmaxf(lmax[p*2+0], v.x + bias[tx * TN + p*2+0]);
            lmax[p*2+1] = fmaxf(lmax[p*2+1], v.y + bias[tx * TN + p*2+1]);
        }
    }
    #pragma unroll
    for (int j = 0; j < TN; j++) red[tx * TN + j][ty] = lmax[j];
    __syncthreads();
    if (tid < BN) {
        float m = __int_as_float(0xFF800000);
        #pragma unroll
        for (int t = 0; t < 16; t++) m = fmaxf(m, red[tid][t]);
        atomicMaxF(&out[tid], m);
    }
}

// ---------------------------------------------------------------------------
// Launch
// ---------------------------------------------------------------------------
extern "C" void kernel_launch(void* const* d_in, const int* in_sizes, int n_in,
                              void* d_out, int out_size)
{
    const float* x    = (const float*)d_in[0];
    const int*   ei   = (const int*)  d_in[1];
    const float* W0   = (const float*)d_in[3];
    const float* b0   = (const float*)d_in[4];
    const float* W1   = (const float*)d_in[5];
    const float* b1   = (const float*)d_in[6];
    const float* W2   = (const float*)d_in[7];
    const float* b2   = (const float*)d_in[8];
    const float* Wlin = (const float*)d_in[9];
    const float* blin = (const float*)d_in[10];
    float* out = (float*)d_out;

    const int n = in_sizes[0] / FIN;
    const int E = in_sizes[1] / 2;

    float *pT, *pA, *pB, *pD;
    int *pCnt, *pOffs, *pCur, *pBs, *pBb, *pSrc;
    cudaGetSymbolAddress((void**)&pT, g_T);
    cudaGetSymbolAddress((void**)&pA, g_A);
    cudaGetSymbolAddress((void**)&pB, g_B);
    cudaGetSymbolAddress((void**)&pD, g_dinv);
    cudaGetSymbolAddress((void**)&pCnt, g_cnt);
    cudaGetSymbolAddress((void**)&pOffs, g_offs);
    cudaGetSymbolAddress((void**)&pCur, g_cursor);
    cudaGetSymbolAddress((void**)&pBs, g_bsum);
    cudaGetSymbolAddress((void**)&pBb, g_bbase);
    cudaGetSymbolAddress((void**)&pSrc, g_ssrc);

    const int nodeBlocks = (n + 255) / 256;
    const int edgeBlocks = (E + 255) / 256;
    const int gemmBlocks = (n + 127) / 128;
    const int scanBlocks = (n + SCAN_B - 1) / SCAN_B;
    const int aggBlocks  = (n + 3) / 4;

    // CSR build + normalization
    zero_cnt_kernel<<<nodeBlocks, 256>>>(pCnt, n);
    hist_kernel<<<edgeBlocks, 256>>>(ei, pCnt, E);
    scan_block_kernel<<<scanBlocks, SCAN_B>>>(pCnt, pOffs, pBs, n);
    scan_top_kernel<<<1, SCAN_B>>>(pBs, pBb, scanBlocks);
    finalize_offs_kernel<<<nodeBlocks, 256>>>(pOffs, pBb, pCur, pCnt, pD, n);
    scatter_edges_kernel<<<edgeBlocks, 256>>>(ei, pCur, pSrc, E);

    // layer 0
    gemm_kernel<FIN, HID><<<gemmBlocks, 256>>>(x, W0, pT, n);
    agg_gather_kernel<<<aggBlocks, 128>>>(pSrc, pOffs, pCnt, pD, b0, pT, pA, n);
    // layer 1
    gemm_kernel<HID, HID><<<gemmBlocks, 256>>>(pA, W1, pT, n);
    agg_gather_kernel<<<aggBlocks, 128>>>(pSrc, pOffs, pCnt, pD, b1, pT, pB, n);
    // layer 2
    gemm_kernel<HID, HID><<<gemmBlocks, 256>>>(pB, W2, pT, n);
    agg_gather_kernel<<<aggBlocks, 128>>>(pSrc, pOffs, pCnt, pD, b2, pT, pA, n);

    // final
    init_out_kernel<<<1, 64>>>(out);
    gemm_max_kernel<<<gemmBlocks, 256>>>(pA, Wlin, blin, out, n);
}

// round 5
// speedup vs baseline: 2.6012x; 1.5638x over previous
#include <cuda_runtime.h>
#include <cstdint>
#include <cstddef>

#define FIN   256
#define HID   128
#define OUTD  64
#define MAXN  50176
#define MAXE  800000
#define SCAN_B 256

typedef unsigned long long ull;

__device__ float g_T[(size_t)MAXN * HID];
__device__ float g_A[(size_t)MAXN * HID];
__device__ float g_B[(size_t)MAXN * HID];
__device__ float g_dinv[MAXN];
__device__ int   g_cnt[MAXN];
__device__ int   g_offs[MAXN];
__device__ int   g_cursor[MAXN];
__device__ int   g_bsum[SCAN_B];
__device__ int   g_bbase[SCAN_B];
__device__ int   g_ssrc[MAXE];

// ---------------------------------------------------------------------------
// PTX helpers
// ---------------------------------------------------------------------------
__device__ __forceinline__ void cp_async16(void* smem_dst, const void* gmem_src) {
    uint32_t s = (uint32_t)__cvta_generic_to_shared(smem_dst);
    asm volatile("cp.async.cg.shared.global [%0], [%1], 16;\n" :: "r"(s), "l"(gmem_src));
}
__device__ __forceinline__ void cp_commit() {
    asm volatile("cp.async.commit_group;\n");
}
template<int N>
__device__ __forceinline__ void cp_wait() {
    asm volatile("cp.async.wait_group %0;\n" :: "n"(N));
}
__device__ __forceinline__ uint32_t f2tf(float f) {
    uint32_t r;
    asm("cvt.rna.tf32.f32 %0, %1;" : "=r"(r) : "f"(f));
    return r;
}
__device__ __forceinline__ void mma_tf32(float c[4], const uint32_t a[4],
                                         uint32_t b0, uint32_t b1) {
    asm volatile(
        "mma.sync.aligned.m16n8k8.row.col.f32.tf32.tf32.f32 "
        "{%0,%1,%2,%3}, {%4,%5,%6,%7}, {%8,%9}, {%0,%1,%2,%3};"
        : "+f"(c[0]), "+f"(c[1]), "+f"(c[2]), "+f"(c[3])
        : "r"(a[0]), "r"(a[1]), "r"(a[2]), "r"(a[3]), "r"(b0), "r"(b1));
}

// ---------------------------------------------------------------------------
// CSR build: histogram -> block scan -> scatter
// ---------------------------------------------------------------------------
__global__ void zero_cnt_kernel(int* cnt, int n) {
    int i = blockIdx.x * blockDim.x + threadIdx.x;
    if (i < n) cnt[i] = 0;
}
__global__ void hist_kernel(const int* __restrict__ ei, int* cnt, int E) {
    int e = blockIdx.x * blockDim.x + threadIdx.x;
    if (e < E) atomicAdd(&cnt[ei[E + e]], 1);
}
__global__ void scan_block_kernel(const int* __restrict__ cnt, int* offs,
                                  int* bsum, int n) {
    __shared__ int sm[SCAN_B];
    int i = blockIdx.x * SCAN_B + threadIdx.x;
    int v = (i < n) ? cnt[i] : 0;
    sm[threadIdx.x] = v;
    __syncthreads();
    #pragma unroll
    for (int o = 1; o < SCAN_B; o <<= 1) {
        int y = (threadIdx.x >= o) ? sm[threadIdx.x - o] : 0;
        __syncthreads();
        sm[threadIdx.x] += y;
        __syncthreads();
    }
    if (i < n) offs[i] = sm[threadIdx.x] - v;
    if (threadIdx.x == SCAN_B - 1) bsum[blockIdx.x] = sm[SCAN_B - 1];
}
__global__ void scan_top_kernel(const int* __restrict__ bsum, int* bbase, int nb) {
    __shared__ int sm[SCAN_B];
    int v = (threadIdx.x < nb) ? bsum[threadIdx.x] : 0;
    sm[threadIdx.x] = v;
    __syncthreads();
    #pragma unroll
    for (int o = 1; o < SCAN_B; o <<= 1) {
        int y = (threadIdx.x >= o) ? sm[threadIdx.x - o] : 0;
        __syncthreads();
        sm[threadIdx.x] += y;
        __syncthreads();
    }
    if (threadIdx.x < nb) bbase[threadIdx.x] = sm[threadIdx.x] - v;
}
__global__ void finalize_offs_kernel(int* offs, const int* __restrict__ bbase,
                                     int* cursor, const int* __restrict__ cnt,
                                     float* dinv, int n) {
    int i = blockIdx.x * blockDim.x + threadIdx.x;
    if (i < n) {
        int o = offs[i] + bbase[i / SCAN_B];
        offs[i] = o;
        cursor[i] = o;
        dinv[i] = rsqrtf((float)(cnt[i] + 1));
    }
}
__global__ void scatter_edges_kernel(const int* __restrict__ ei, int* cursor,
                                     int* ssrc, int E) {
    int e = blockIdx.x * blockDim.x + threadIdx.x;
    if (e < E) {
        int s = ei[e];
        int d = ei[E + e];
        int p = atomicAdd(&cursor[d], 1);
        ssrc[p] = s;
    }
}

// ---------------------------------------------------------------------------
// TF32 tensor-core GEMM core.
// BM=128, BK=16, double-buffered cp.async. 8 warps: 4 m-groups x 2 n-groups,
// warp tile 32 x (BN/2) of m16n8k8 MMAs.
//   As[128][20]  (row-major, pad 20 -> conflict-free fragment LDS)
//   Ws[16][BN+8] ([k][n], pad +8 -> conflict-free B-fragment LDS)
// ---------------------------------------------------------------------------
#define APAD 20

template<int K, int BN>
struct TCore {
    static constexpr int WPAD = BN + 8;
    static constexpr int NTN  = (BN / 2) / 8;   // n-tiles per warp

    static __device__ __forceinline__
    void loadA(float (*As)[APAD], const float* __restrict__ A,
               int rowBase, int kt, int n, int tid) {
        // 128 rows x 16 floats = 512 x 16B chunks, 2 per thread
        #pragma unroll
        for (int i = 0; i < 2; i++) {
            int ch  = i * 256 + tid;
            int row = ch >> 2;
            int cin = (ch & 3) * 4;
            int grow = rowBase + row;
            if (grow >= n) grow = n - 1;
            cp_async16(&As[row][cin], A + (size_t)grow * K + kt + cin);
        }
    }
    static __device__ __forceinline__
    void loadW(float (*Ws)[WPAD], const float* __restrict__ W, int kt, int tid) {
        constexpr int CPK = BN / 4;          // 16B chunks per k-row
        constexpr int NCH = 16 * CPK;
        #pragma unroll
        for (int i = 0; i < NCH / 256; i++) {
            int ch  = i * 256 + tid;
            int k   = ch / CPK;
            int cin = (ch % CPK) * 4;
            cp_async16(&Ws[k][cin], W + (size_t)(kt + k) * BN + cin);
        }
    }
    static __device__ __forceinline__
    void compute(const float (*As)[APAD], const float (*Ws)[WPAD],
                 float acc[2][NTN][4], int m0, int n0, int lane) {
        const int gid = lane >> 2;       // group id 0..7
        const int tig = lane & 3;        // thread in group 0..3
        #pragma unroll
        for (int kk = 0; kk < 16; kk += 8) {
            uint32_t a[2][4];
            #pragma unroll
            for (int mt = 0; mt < 2; mt++) {
                int r = m0 + mt * 16 + gid;
                int c = kk + tig;
                a[mt][0] = f2tf(As[r    ][c    ]);
                a[mt][1] = f2tf(As[r + 8][c    ]);
                a[mt][2] = f2tf(As[r    ][c + 4]);
                a[mt][3] = f2tf(As[r + 8][c + 4]);
            }
            #pragma unroll
            for (int nt = 0; nt < NTN; nt++) {
                int c  = n0 + nt * 8 + gid;
                int kb = kk + tig;
                uint32_t b0 = f2tf(Ws[kb    ][c]);
                uint32_t b1 = f2tf(Ws[kb + 4][c]);
                mma_tf32(acc[0][nt], a[0], b0, b1);
                mma_tf32(acc[1][nt], a[1], b0, b1);
            }
        }
    }
};

// ---------------------------------------------------------------------------
// Plain TF32 GEMM: T = A @ W
// ---------------------------------------------------------------------------
template<int K, int BN>
__global__ void __launch_bounds__(256, 2)
gemm_tf32_kernel(const float* __restrict__ A, const float* __restrict__ W,
                 float* __restrict__ T, int n)
{
    using C = TCore<K, BN>;
    constexpr int NTN = C::NTN;
    constexpr int NT  = K / 16;

    __shared__ float As[2][128][APAD];
    __shared__ float Ws[2][16][C::WPAD];

    const int tid  = threadIdx.x;
    const int wid  = tid >> 5, lane = tid & 31;
    const int m0   = (wid >> 1) * 32;
    const int n0   = (wid & 1) * (BN / 2);
    const int rowBase = blockIdx.x * 128;

    float acc[2][NTN][4];
    #pragma unroll
    for (int mt = 0; mt < 2; mt++)
        #pragma unroll
        for (int nt = 0; nt < NTN; nt++)
            #pragma unroll
            for (int q = 0; q < 4; q++) acc[mt][nt][q] = 0.0f;

    C::loadA(As[0], A, rowBase, 0, n, tid);
    C::loadW(Ws[0], W, 0, tid);
    cp_commit();

    #pragma unroll 1
    for (int t = 0; t < NT; t++) {
        int cur = t & 1, nxt = cur ^ 1;
        if (t + 1 < NT) {
            C::loadA(As[nxt], A, rowBase, (t + 1) * 16, n, tid);
            C::loadW(Ws[nxt], W, (t + 1) * 16, tid);
        }
        cp_commit();
        cp_wait<1>();
        __syncthreads();
        C::compute(As[cur], Ws[cur], acc, m0, n0, lane);
        __syncthreads();
    }

    const int gid = lane >> 2, tig = lane & 3;
    #pragma unroll
    for (int mt = 0; mt < 2; mt++) {
        #pragma unroll
        for (int nt = 0; nt < NTN; nt++) {
            int r = rowBase + m0 + mt * 16 + gid;
            int c = n0 + nt * 8 + tig * 2;
            if (r < n)
                *reinterpret_cast<float2*>(T + (size_t)r * BN + c) =
                    make_float2(acc[mt][nt][0], acc[mt][nt][1]);
            if (r + 8 < n)
                *reinterpret_cast<float2*>(T + (size_t)(r + 8) * BN + c) =
                    make_float2(acc[mt][nt][2], acc[mt][nt][3]);
        }
    }
}

// ---------------------------------------------------------------------------
// Gather aggregation (unchanged): one warp per node, CSR walk, no atomics.
// ---------------------------------------------------------------------------
__global__ void __launch_bounds__(128)
agg_gather_kernel(const int* __restrict__ ssrc, const int* __restrict__ offs,
                  const int* __restrict__ cnt, const float* __restrict__ dinv,
                  const float* __restrict__ bias, const float* __restrict__ T,
                  float* __restrict__ G, int n)
{
    int node = blockIdx.x * 4 + (threadIdx.x >> 5);
    if (node >= n) return;
    int lane = threadIdx.x & 31;

    float dv = dinv[node];
    float4 t = *reinterpret_cast<const float4*>(T + (size_t)node * HID + lane * 4);
    float4 b = *reinterpret_cast<const float4*>(bias + lane * 4);
    float d2 = dv * dv;
    float4 acc = make_float4(d2 * t.x + b.x, d2 * t.y + b.y,
                             d2 * t.z + b.z, d2 * t.w + b.w);

    int beg = offs[node];
    int end = beg + cnt[node];
    int e = beg;
    for (; e + 1 < end; e += 2) {
        int s0 = ssrc[e], s1 = ssrc[e + 1];
        float n0 = dinv[s0] * dv, n1 = dinv[s1] * dv;
        float4 v0 = *reinterpret_cast<const float4*>(T + (size_t)s0 * HID + lane * 4);
        float4 v1 = *reinterpret_cast<const float4*>(T + (size_t)s1 * HID + lane * 4);
        acc.x += n0 * v0.x + n1 * v1.x;
        acc.y += n0 * v0.y + n1 * v1.y;
        acc.z += n0 * v0.z + n1 * v1.z;
        acc.w += n0 * v0.w + n1 * v1.w;
    }
    if (e < end) {
        int s0 = ssrc[e];
        float n0 = dinv[s0] * dv;
        float4 v0 = *reinterpret_cast<const float4*>(T + (size_t)s0 * HID + lane * 4);
        acc.x += n0 * v0.x; acc.y += n0 * v0.y;
        acc.z += n0 * v0.z; acc.w += n0 * v0.w;
    }
    *reinterpret_cast<float4*>(G + (size_t)node * HID + lane * 4) = acc;
}

// ---------------------------------------------------------------------------
// Final layer TF32 GEMM + fused global max-pool (BN=64)
// ---------------------------------------------------------------------------
__device__ __forceinline__ void atomicMaxF(float* addr, float v) {
    if (v >= 0.0f) atomicMax((int*)addr, __float_as_int(v));
    else           atomicMin((unsigned int*)addr, __float_as_uint(v));
}

__global__ void init_out_kernel(float* out) {
    if (threadIdx.x < OUTD) out[threadIdx.x] = __int_as_float(0xFF800000);
}

__global__ void __launch_bounds__(256, 2)
gemm_max_tf32_kernel(const float* __restrict__ A, const float* __restrict__ W,
                     const float* __restrict__ bias, float* __restrict__ out, int n)
{
    constexpr int K = HID, BN = OUTD;
    using C = TCore<K, BN>;
    constexpr int NTN = C::NTN;      // 4
    constexpr int NT  = K / 16;

    __shared__ float As[2][128][APAD];
    __shared__ float Ws[2][16][C::WPAD];
    __shared__ float red[OUTD];

    const int tid  = threadIdx.x;
    const int wid  = tid >> 5, lane = tid & 31;
    const int m0   = (wid >> 1) * 32;
    const int n0   = (wid & 1) * (BN / 2);
    const int rowBase = blockIdx.x * 128;

    if (tid < OUTD) red[tid] = __int_as_float(0xFF800000);

    float acc[2][NTN][4];
    #pragma unroll
    for (int mt = 0; mt < 2; mt++)
        #pragma unroll
        for (int nt = 0; nt < NTN; nt++)
            #pragma unroll
            for (int q = 0; q < 4; q++) acc[mt][nt][q] = 0.0f;

    C::loadA(As[0], A, rowBase, 0, n, tid);
    C::loadW(Ws[0], W, 0, tid);
    cp_commit();

    #pragma unroll 1
    for (int t = 0; t < NT; t++) {
        int cur = t & 1, nxt = cur ^ 1;
        if (t + 1 < NT) {
            C::loadA(As[nxt], A, rowBase, (t + 1) * 16, n, tid);
            C::loadW(Ws[nxt], W, (t + 1) * 16, tid);
        }
        cp_commit();
        cp_wait<1>();
        __syncthreads();
        C::compute(As[cur], Ws[cur], acc, m0, n0, lane);
        __syncthreads();
    }

    // Row-clamped OOB rows duplicate valid row n-1 -> harmless under max.
    const int tig = lane & 3;
    #pragma unroll
    for (int nt = 0; nt < NTN; nt++) {
        int c = n0 + nt * 8 + tig * 2;
        float m0v = fmaxf(fmaxf(acc[0][nt][0], acc[0][nt][2]),
                          fmaxf(acc[1][nt][0], acc[1][nt][2]));
        float m1v = fmaxf(fmaxf(acc[0][nt][1], acc[0][nt][3]),
                          fmaxf(acc[1][nt][1], acc[1][nt][3]));
        atomicMaxF(&red[c],     m0v + bias[c]);
        atomicMaxF(&red[c + 1], m1v + bias[c + 1]);
    }
    __syncthreads();
    if (tid < OUTD) atomicMaxF(&out[tid], red[tid]);
}

// ---------------------------------------------------------------------------
// Launch
// ---------------------------------------------------------------------------
extern "C" void kernel_launch(void* const* d_in, const int* in_sizes, int n_in,
                              void* d_out, int out_size)
{
    const float* x    = (const float*)d_in[0];
    const int*   ei   = (const int*)  d_in[1];
    const float* W0   = (const float*)d_in[3];
    const float* b0   = (const float*)d_in[4];
    const float* W1   = (const float*)d_in[5];
    const float* b1   = (const float*)d_in[6];
    const float* W2   = (const float*)d_in[7];
    const float* b2   = (const float*)d_in[8];
    const float* Wlin = (const float*)d_in[9];
    const float* blin = (const float*)d_in[10];
    float* out = (float*)d_out;

    const int n = in_sizes[0] / FIN;
    const int E = in_sizes[1] / 2;

    float *pT, *pA, *pB, *pD;
    int *pCnt, *pOffs, *pCur, *pBs, *pBb, *pSrc;
    cudaGetSymbolAddress((void**)&pT, g_T);
    cudaGetSymbolAddress((void**)&pA, g_A);
    cudaGetSymbolAddress((void**)&pB, g_B);
    cudaGetSymbolAddress((void**)&pD, g_dinv);
    cudaGetSymbolAddress((void**)&pCnt, g_cnt);
    cudaGetSymbolAddress((void**)&pOffs, g_offs);
    cudaGetSymbolAddress((void**)&pCur, g_cursor);
    cudaGetSymbolAddress((void**)&pBs, g_bsum);
    cudaGetSymbolAddress((void**)&pBb, g_bbase);
    cudaGetSymbolAddress((void**)&pSrc, g_ssrc);

    const int nodeBlocks = (n + 255) / 256;
    const int edgeBlocks = (E + 255) / 256;
    const int gemmBlocks = (n + 127) / 128;
    const int scanBlocks = (n + SCAN_B - 1) / SCAN_B;
    const int aggBlocks  = (n + 3) / 4;

    // CSR build + normalization
    zero_cnt_kernel<<<nodeBlocks, 256>>>(pCnt, n);
    hist_kernel<<<edgeBlocks, 256>>>(ei, pCnt, E);
    scan_block_kernel<<<scanBlocks, SCAN_B>>>(pCnt, pOffs, pBs, n);
    scan_top_kernel<<<1, SCAN_B>>>(pBs, pBb, scanBlocks);
    finalize_offs_kernel<<<nodeBlocks, 256>>>(pOffs, pBb, pCur, pCnt, pD, n);
    scatter_edges_kernel<<<edgeBlocks, 256>>>(ei, pCur, pSrc, E);

    // layer 0
    gemm_tf32_kernel<FIN, HID><<<gemmBlocks, 256>>>(x, W0, pT, n);
    agg_gather_kernel<<<aggBlocks, 128>>>(pSrc, pOffs, pCnt, pD, b0, pT, pA, n);
    // layer 1
    gemm_tf32_kernel<HID, HID><<<gemmBlocks, 256>>>(pA, W1, pT, n);
    agg_gather_kernel<<<aggBlocks, 128>>>(pSrc, pOffs, pCnt, pD, b1, pT, pB, n);
    // layer 2
    gemm_tf32_kernel<HID, HID><<<gemmBlocks, 256>>>(pB, W2, pT, n);
    agg_gather_kernel<<<aggBlocks, 128>>>(pSrc, pOffs, pCnt, pD, b2, pT, pA, n);

    // final
    init_out_kernel<<<1, 64>>>(out);
    gemm_max_tf32_kernel<<<gemmBlocks, 256>>>(pA, Wlin, blin, out, n);
}